// round 2
// baseline (speedup 1.0000x reference)
#include <cuda_runtime.h>
#include <math.h>

#define N_MAX 100000
#define E_MAX 1600000
#define DH 128
#define DOUT 40
#define BN_EPS 1e-5f

// ---------------- scratch (static device globals; no allocation) ----------------
__device__ float g_disq[N_MAX];                       // deg -> d^-1/2
__device__ float g_norme[E_MAX];                      // edge norm
__device__ float g_t[(size_t)N_MAX * DH];             // t = h @ W
__device__ float g_agg[(size_t)N_MAX * DH];           // segment sum
__device__ float g_h[(size_t)N_MAX * DH];             // pre-BN layer output
__device__ float g_stats[2 * DH];                     // colsum, colsumsq
__device__ float g_scale[DH];                         // BN fused scale
__device__ float g_shift[DH];                         // BN fused shift

// ---------------- helpers ----------------
__device__ __forceinline__ void red_add_v4(float* p, float4 v) {
    asm volatile("red.global.add.v4.f32 [%0], {%1,%2,%3,%4};"
                 :: "l"(p), "f"(v.x), "f"(v.y), "f"(v.z), "f"(v.w) : "memory");
}

// ---------------- degree / normalization ----------------
__global__ void init_deg(int n) {
    int i = blockIdx.x * blockDim.x + threadIdx.x;
    if (i < n) g_disq[i] = 1.0f;
}
__global__ void count_deg(const int* __restrict__ dst, int e) {
    int i = blockIdx.x * blockDim.x + threadIdx.x;
    if (i < e) atomicAdd(&g_disq[dst[i]], 1.0f);
}
__global__ void to_disq(int n) {
    int i = blockIdx.x * blockDim.x + threadIdx.x;
    if (i < n) g_disq[i] = rsqrtf(g_disq[i]);
}
__global__ void calc_norme(const int* __restrict__ src, const int* __restrict__ dst, int e) {
    int i = blockIdx.x * blockDim.x + threadIdx.x;
    if (i < e) g_norme[i] = g_disq[src[i]] * g_disq[dst[i]];
}

// ---------------- zero kernels ----------------
__global__ void zero_agg(long long n4) {
    long long i = (long long)blockIdx.x * blockDim.x + threadIdx.x;
    if (i < n4) ((float4*)g_agg)[i] = make_float4(0.f, 0.f, 0.f, 0.f);
}
__global__ void zero_stats() {
    int i = threadIdx.x;
    if (i < 2 * DH) g_stats[i] = 0.0f;
}

// ---------------- GEMM 128x128 (BM=64, BK=32, BN=128), optional fused BN+ReLU on load ----------------
__global__ void __launch_bounds__(256) gemm128(const float* __restrict__ Xin,
                                               const float* __restrict__ W,
                                               int n, int use_bn) {
    __shared__ float xs[64][32];
    __shared__ float ws[32][128];
    const float* X = Xin ? Xin : g_h;

    int tid  = threadIdx.x;
    int row0 = blockIdx.x * 64;
    int colg = tid & 31;       // 32 col groups * 4 cols
    int rowg = tid >> 5;       // 8 row groups * 8 rows

    float acc[8][4];
#pragma unroll
    for (int i = 0; i < 8; i++)
#pragma unroll
        for (int j = 0; j < 4; j++) acc[i][j] = 0.f;

    for (int kc = 0; kc < 4; kc++) {
        // load X tile 64x32 (512 float4)
#pragma unroll
        for (int t = 0; t < 2; t++) {
            int i  = tid + t * 256;
            int r  = i >> 3;
            int c4 = i & 7;
            int gr = row0 + r;
            float4 v = make_float4(0.f, 0.f, 0.f, 0.f);
            if (gr < n) v = *(const float4*)(X + (size_t)gr * DH + kc * 32 + c4 * 4);
            if (use_bn) {
                float4 sc = *(const float4*)(g_scale + kc * 32 + c4 * 4);
                float4 sh = *(const float4*)(g_shift + kc * 32 + c4 * 4);
                v.x = fmaxf(0.f, fmaf(v.x, sc.x, sh.x));
                v.y = fmaxf(0.f, fmaf(v.y, sc.y, sh.y));
                v.z = fmaxf(0.f, fmaf(v.z, sc.z, sh.z));
                v.w = fmaxf(0.f, fmaf(v.w, sc.w, sh.w));
            }
            *(float4*)&xs[r][c4 * 4] = v;
        }
        // load W tile 32x128 (1024 float4)
#pragma unroll
        for (int t = 0; t < 4; t++) {
            int i  = tid + t * 256;
            int r  = i >> 5;
            int c4 = i & 31;
            *(float4*)&ws[r][c4 * 4] = *(const float4*)(W + (size_t)(kc * 32 + r) * DH + c4 * 4);
        }
        __syncthreads();
#pragma unroll
        for (int kk = 0; kk < 32; kk++) {
            float4 wv = *(float4*)&ws[kk][colg * 4];
#pragma unroll
            for (int i = 0; i < 8; i++) {
                float xv = xs[rowg * 8 + i][kk];
                acc[i][0] = fmaf(xv, wv.x, acc[i][0]);
                acc[i][1] = fmaf(xv, wv.y, acc[i][1]);
                acc[i][2] = fmaf(xv, wv.z, acc[i][2]);
                acc[i][3] = fmaf(xv, wv.w, acc[i][3]);
            }
        }
        __syncthreads();
    }
#pragma unroll
    for (int i = 0; i < 8; i++) {
        int gr = row0 + rowg * 8 + i;
        if (gr < n)
            *(float4*)(g_t + (size_t)gr * DH + colg * 4) =
                make_float4(acc[i][0], acc[i][1], acc[i][2], acc[i][3]);
    }
}

// ---------------- GEMM 128x40 (input = g_h with fused BN+ReLU), writes g_t[n,40] ----------------
__global__ void __launch_bounds__(240) gemm40(const float* __restrict__ W, int n) {
    __shared__ float ws[DH * DOUT];   // 20 KB
    __shared__ float xs[48][32];      // 6 KB

    int tx  = threadIdx.x;            // 0..39 (col)
    int ty  = threadIdx.y;            // 0..5
    int tid = ty * 40 + tx;

    for (int i = tid; i < DH * DOUT; i += 240) ws[i] = W[i];

    int row0 = blockIdx.x * 48;
    float acc[8];
#pragma unroll
    for (int r = 0; r < 8; r++) acc[r] = 0.f;

    for (int kc = 0; kc < 4; kc++) {
        for (int i = tid; i < 384; i += 240) {   // 48x32 = 384 float4
            int r  = i >> 3;
            int c4 = i & 7;
            int gr = row0 + r;
            float4 v = make_float4(0.f, 0.f, 0.f, 0.f);
            if (gr < n) v = *(const float4*)(g_h + (size_t)gr * DH + kc * 32 + c4 * 4);
            float4 sc = *(const float4*)(g_scale + kc * 32 + c4 * 4);
            float4 sh = *(const float4*)(g_shift + kc * 32 + c4 * 4);
            v.x = fmaxf(0.f, fmaf(v.x, sc.x, sh.x));
            v.y = fmaxf(0.f, fmaf(v.y, sc.y, sh.y));
            v.z = fmaxf(0.f, fmaf(v.z, sc.z, sh.z));
            v.w = fmaxf(0.f, fmaf(v.w, sc.w, sh.w));
            *(float4*)&xs[r][c4 * 4] = v;
        }
        __syncthreads();
#pragma unroll
        for (int kk = 0; kk < 32; kk++) {
            float wv = ws[(kc * 32 + kk) * DOUT + tx];
#pragma unroll
            for (int r8 = 0; r8 < 8; r8++)
                acc[r8] = fmaf(xs[ty * 8 + r8][kk], wv, acc[r8]);
        }
        __syncthreads();
    }
#pragma unroll
    for (int r8 = 0; r8 < 8; r8++) {
        int gr = row0 + ty * 8 + r8;
        if (gr < n) g_t[(size_t)gr * DOUT + tx] = acc[r8];
    }
}

// ---------------- edge scatter, F=128: one warp per edge ----------------
__global__ void scatter128(const int* __restrict__ src, const int* __restrict__ dst, int e) {
    long long gid = (long long)blockIdx.x * blockDim.x + threadIdx.x;
    int warp = (int)(gid >> 5);
    int lane = (int)(gid & 31);
    if (warp >= e) return;
    int   s = __ldg(src + warp);
    int   d = __ldg(dst + warp);
    float w = g_norme[warp];
    float4 v = __ldg((const float4*)(g_t + (size_t)s * DH) + lane);
    v.x *= w; v.y *= w; v.z *= w; v.w *= w;
    red_add_v4(g_agg + (size_t)d * DH + lane * 4, v);
}

// ---------------- edge scatter, F=40: one thread per (edge, float4 chunk) ----------------
__global__ void scatter40(const int* __restrict__ src, const int* __restrict__ dst, int e) {
    long long i = (long long)blockIdx.x * blockDim.x + threadIdx.x;
    if (i >= (long long)e * 10) return;
    int ee = (int)(i / 10);
    int c  = (int)(i - (long long)ee * 10);
    int   s = __ldg(src + ee);
    int   d = __ldg(dst + ee);
    float w = g_norme[ee];
    float4 v = __ldg((const float4*)(g_t + (size_t)s * DOUT + c * 4));
    v.x *= w; v.y *= w; v.z *= w; v.w *= w;
    red_add_v4(g_agg + (size_t)d * DOUT + c * 4, v);
}

// ---------------- combine (agg + t*self_norm + b) + column stats, F=128 ----------------
__global__ void combine128(const float* __restrict__ b, int n) {
    int col = threadIdx.x;   // 0..127
    int ty  = threadIdx.y;   // 0..1
    float bc = b[col];
    float s = 0.f, ss = 0.f;
    for (int row = blockIdx.x * 2 + ty; row < n; row += gridDim.x * 2) {
        float sn = g_disq[row];
        sn *= sn;
        size_t off = (size_t)row * DH + col;
        float h = fmaf(g_t[off], sn, g_agg[off]) + bc;
        g_h[off] = h;
        s += h;
        ss = fmaf(h, h, ss);
    }
    __shared__ float sm[2][DH];
    __shared__ float sm2[2][DH];
    sm[ty][col]  = s;
    sm2[ty][col] = ss;
    __syncthreads();
    if (ty == 0) {
        atomicAdd(&g_stats[col],       sm[0][col] + sm[1][col]);
        atomicAdd(&g_stats[DH + col],  sm2[0][col] + sm2[1][col]);
    }
}

// ---------------- BN finalize: scale/shift ----------------
__global__ void bn_finalize(const float* __restrict__ gam, const float* __restrict__ bet, int n) {
    int c = threadIdx.x;
    if (c < DH) {
        float inv_n = 1.0f / (float)n;
        float mu  = g_stats[c] * inv_n;
        float var = g_stats[DH + c] * inv_n - mu * mu;
        float rs  = rsqrtf(var + BN_EPS);
        float sc  = rs * gam[c];
        g_scale[c] = sc;
        g_shift[c] = bet[c] - mu * sc;
    }
}

// ---------------- combine F=40 + log_softmax: one warp per row ----------------
__global__ void combine40_lsm(const float* __restrict__ b2, float* __restrict__ out, int n) {
    long long gid = (long long)blockIdx.x * blockDim.x + threadIdx.x;
    int row  = (int)(gid >> 5);
    int lane = (int)(gid & 31);
    if (row >= n) return;
    float sn = g_disq[row];
    sn *= sn;
    size_t off = (size_t)row * DOUT;

    float h1 = fmaf(g_t[off + lane], sn, g_agg[off + lane]) + b2[lane];
    float h2 = -1e30f;
    if (lane < 8)
        h2 = fmaf(g_t[off + 32 + lane], sn, g_agg[off + 32 + lane]) + b2[32 + lane];

    float m = fmaxf(h1, h2);
#pragma unroll
    for (int o = 16; o; o >>= 1) m = fmaxf(m, __shfl_xor_sync(0xFFFFFFFFu, m, o));
    float se = expf(h1 - m) + (lane < 8 ? expf(h2 - m) : 0.f);
#pragma unroll
    for (int o = 16; o; o >>= 1) se += __shfl_xor_sync(0xFFFFFFFFu, se, o);
    float lse = m + logf(se);

    out[off + lane] = h1 - lse;
    if (lane < 8) out[off + 32 + lane] = h2 - lse;
}

// ---------------- launch ----------------
extern "C" void kernel_launch(void* const* d_in, const int* in_sizes, int n_in,
                              void* d_out, int out_size) {
    const float* x   = (const float*)d_in[0];
    const int*   src = (const int*)d_in[1];
    const int*   dst = (const int*)d_in[2];
    const float* W0  = (const float*)d_in[3];
    const float* b0  = (const float*)d_in[4];
    const float* W1  = (const float*)d_in[5];
    const float* b1  = (const float*)d_in[6];
    const float* W2  = (const float*)d_in[7];
    const float* b2  = (const float*)d_in[8];
    const float* g0  = (const float*)d_in[9];
    const float* be0 = (const float*)d_in[10];
    const float* g1  = (const float*)d_in[11];
    const float* be1 = (const float*)d_in[12];
    float* out = (float*)d_out;

    int n = in_sizes[0] / DH;
    int e = in_sizes[1];

    // normalization precompute
    init_deg<<<(n + 255) / 256, 256>>>(n);
    count_deg<<<(e + 255) / 256, 256>>>(dst, e);
    to_disq<<<(n + 255) / 256, 256>>>(n);
    calc_norme<<<(e + 255) / 256, 256>>>(src, dst, e);

    long long agg4_128 = (long long)n * 32;
    long long agg4_40  = (long long)n * 10;
    int scat128_blocks = (int)(((long long)e * 32 + 255) / 256);
    int scat40_blocks  = (int)(((long long)e * 10 + 255) / 256);
    int lsm_blocks     = (int)(((long long)n * 32 + 255) / 256);

    // ---- layer 0 ----
    zero_agg<<<(int)((agg4_128 + 255) / 256), 256>>>(agg4_128);
    gemm128<<<(n + 63) / 64, 256>>>(x, W0, n, 0);
    scatter128<<<scat128_blocks, 256>>>(src, dst, e);
    zero_stats<<<1, 256>>>();
    combine128<<<1024, dim3(DH, 2)>>>(b0, n);
    bn_finalize<<<1, DH>>>(g0, be0, n);

    // ---- layer 1 ----
    zero_agg<<<(int)((agg4_128 + 255) / 256), 256>>>(agg4_128);
    gemm128<<<(n + 63) / 64, 256>>>(nullptr, W1, n, 1);   // BN0+ReLU fused on load
    scatter128<<<scat128_blocks, 256>>>(src, dst, e);
    zero_stats<<<1, 256>>>();
    combine128<<<1024, dim3(DH, 2)>>>(b1, n);
    bn_finalize<<<1, DH>>>(g1, be1, n);

    // ---- layer 2 ----
    zero_agg<<<(int)((agg4_40 + 255) / 256), 256>>>(agg4_40);
    gemm40<<<(n + 47) / 48, dim3(DOUT, 6)>>>(W2, n);      // BN1+ReLU fused on load
    scatter40<<<scat40_blocks, 256>>>(src, dst, e);
    combine40_lsm<<<lsm_blocks, 256>>>(b2, out, n);
}

// round 3
// speedup vs baseline: 1.6084x; 1.6084x over previous
#include <cuda_runtime.h>
#include <math.h>

#define N_MAX 100000
#define E_MAX 1600000
#define DH 128
#define DOUT 40
#define BN_EPS 1e-5f
#define SCAN_B 1024
#define NB_MAX 128   // ceil(N_MAX/1024) = 98

// ---------------- scratch (static device globals; no allocation) ----------------
__device__ int   g_deg[N_MAX];                        // in-degree (without self loop)
__device__ int   g_incl[N_MAX];                       // per-block inclusive scan
__device__ int   g_bsum[NB_MAX];                      // block sums
__device__ int   g_bscan[NB_MAX];                     // scanned block sums (inclusive)
__device__ int   g_rowstart[N_MAX];                   // CSR row start
__device__ int   g_cursor[N_MAX];                     // fill cursor
__device__ float g_disq[N_MAX];                       // d^-1/2 (deg incl self loop)
__device__ int2  g_csr[E_MAX];                        // {src, bitcast(norm_w)}
__device__ float g_t[(size_t)N_MAX * DH];             // t = h @ W
__device__ float g_h[(size_t)N_MAX * DH];             // pre-BN layer output
__device__ float g_stats[2 * DH];                     // colsum, colsumsq
__device__ float g_scale[DH];                         // BN fused scale
__device__ float g_shift[DH];                         // BN fused shift

// ---------------- helpers ----------------
__device__ __forceinline__ void red_add_v4(float* p, float4 v) {
    asm volatile("red.global.add.v4.f32 [%0], {%1,%2,%3,%4};"
                 :: "l"(p), "f"(v.x), "f"(v.y), "f"(v.z), "f"(v.w) : "memory");
}

// ---------------- CSR build ----------------
__global__ void zero_deg(int n) {
    int i = blockIdx.x * blockDim.x + threadIdx.x;
    if (i < n) g_deg[i] = 0;
}
__global__ void count_deg(const int* __restrict__ dst, int e) {
    int i = blockIdx.x * blockDim.x + threadIdx.x;
    if (i < e) atomicAdd(&g_deg[dst[i]], 1);
}
__global__ void calc_disq(int n) {
    int i = blockIdx.x * blockDim.x + threadIdx.x;
    if (i < n) g_disq[i] = rsqrtf(1.0f + (float)g_deg[i]);
}
// per-block inclusive scan of g_deg -> g_incl, block totals -> g_bsum
__global__ void scan1(int n) {
    __shared__ int sm[SCAN_B];
    int tid = threadIdx.x;
    int i = blockIdx.x * SCAN_B + tid;
    sm[tid] = (i < n) ? g_deg[i] : 0;
    __syncthreads();
#pragma unroll
    for (int off = 1; off < SCAN_B; off <<= 1) {
        int t = (tid >= off) ? sm[tid - off] : 0;
        __syncthreads();
        sm[tid] += t;
        __syncthreads();
    }
    if (i < n) g_incl[i] = sm[tid];
    if (tid == SCAN_B - 1) g_bsum[blockIdx.x] = sm[tid];
}
// single-block inclusive scan of block sums
__global__ void scan2(int nb) {
    __shared__ int sm[NB_MAX];
    int tid = threadIdx.x;
    sm[tid] = (tid < nb) ? g_bsum[tid] : 0;
    __syncthreads();
#pragma unroll
    for (int off = 1; off < NB_MAX; off <<= 1) {
        int t = (tid >= off) ? sm[tid - off] : 0;
        __syncthreads();
        sm[tid] += t;
        __syncthreads();
    }
    if (tid < nb) g_bscan[tid] = sm[tid];
}
// row_start[i] = exclusive scan; also init cursor
__global__ void scan3(int n) {
    int i = blockIdx.x * blockDim.x + threadIdx.x;
    if (i < n) {
        int b = i / SCAN_B;
        int base = (b > 0) ? g_bscan[b - 1] : 0;
        int rs = base + g_incl[i] - g_deg[i];
        g_rowstart[i] = rs;
        g_cursor[i]   = rs;
    }
}
__global__ void fill_csr(const int* __restrict__ src, const int* __restrict__ dst, int e) {
    int i = blockIdx.x * blockDim.x + threadIdx.x;
    if (i < e) {
        int s = src[i], d = dst[i];
        int pos = atomicAdd(&g_cursor[d], 1);
        float w = g_disq[s] * g_disq[d];
        g_csr[pos] = make_int2(s, __float_as_int(w));
    }
}

__global__ void zero_stats() {
    int i = threadIdx.x;
    if (i < 2 * DH) g_stats[i] = 0.0f;
}

// ---------------- GEMM 128x128 (BM=64, BK=32, BN=128), optional fused BN+ReLU on load ----------------
__global__ void __launch_bounds__(256) gemm128(const float* __restrict__ Xin,
                                               const float* __restrict__ W,
                                               int n, int use_bn) {
    __shared__ float xs[64][32];
    __shared__ float ws[32][128];
    const float* X = Xin ? Xin : g_h;

    int tid  = threadIdx.x;
    int row0 = blockIdx.x * 64;
    int colg = tid & 31;
    int rowg = tid >> 5;

    float acc[8][4];
#pragma unroll
    for (int i = 0; i < 8; i++)
#pragma unroll
        for (int j = 0; j < 4; j++) acc[i][j] = 0.f;

    for (int kc = 0; kc < 4; kc++) {
#pragma unroll
        for (int t = 0; t < 2; t++) {
            int i  = tid + t * 256;
            int r  = i >> 3;
            int c4 = i & 7;
            int gr = row0 + r;
            float4 v = make_float4(0.f, 0.f, 0.f, 0.f);
            if (gr < n) v = *(const float4*)(X + (size_t)gr * DH + kc * 32 + c4 * 4);
            if (use_bn) {
                float4 sc = *(const float4*)(g_scale + kc * 32 + c4 * 4);
                float4 sh = *(const float4*)(g_shift + kc * 32 + c4 * 4);
                v.x = fmaxf(0.f, fmaf(v.x, sc.x, sh.x));
                v.y = fmaxf(0.f, fmaf(v.y, sc.y, sh.y));
                v.z = fmaxf(0.f, fmaf(v.z, sc.z, sh.z));
                v.w = fmaxf(0.f, fmaf(v.w, sc.w, sh.w));
            }
            *(float4*)&xs[r][c4 * 4] = v;
        }
#pragma unroll
        for (int t = 0; t < 4; t++) {
            int i  = tid + t * 256;
            int r  = i >> 5;
            int c4 = i & 31;
            *(float4*)&ws[r][c4 * 4] = *(const float4*)(W + (size_t)(kc * 32 + r) * DH + c4 * 4);
        }
        __syncthreads();
#pragma unroll
        for (int kk = 0; kk < 32; kk++) {
            float4 wv = *(float4*)&ws[kk][colg * 4];
#pragma unroll
            for (int i = 0; i < 8; i++) {
                float xv = xs[rowg * 8 + i][kk];
                acc[i][0] = fmaf(xv, wv.x, acc[i][0]);
                acc[i][1] = fmaf(xv, wv.y, acc[i][1]);
                acc[i][2] = fmaf(xv, wv.z, acc[i][2]);
                acc[i][3] = fmaf(xv, wv.w, acc[i][3]);
            }
        }
        __syncthreads();
    }
#pragma unroll
    for (int i = 0; i < 8; i++) {
        int gr = row0 + rowg * 8 + i;
        if (gr < n)
            *(float4*)(g_t + (size_t)gr * DH + colg * 4) =
                make_float4(acc[i][0], acc[i][1], acc[i][2], acc[i][3]);
    }
}

// ---------------- GEMM 128x40 (input = g_h with fused BN+ReLU), writes g_t[n,40] ----------------
__global__ void __launch_bounds__(240) gemm40(const float* __restrict__ W, int n) {
    __shared__ float ws[DH * DOUT];
    __shared__ float xs[48][32];

    int tx  = threadIdx.x;
    int ty  = threadIdx.y;
    int tid = ty * 40 + tx;

    for (int i = tid; i < DH * DOUT; i += 240) ws[i] = W[i];

    int row0 = blockIdx.x * 48;
    float acc[8];
#pragma unroll
    for (int r = 0; r < 8; r++) acc[r] = 0.f;

    for (int kc = 0; kc < 4; kc++) {
        for (int i = tid; i < 384; i += 240) {
            int r  = i >> 3;
            int c4 = i & 7;
            int gr = row0 + r;
            float4 v = make_float4(0.f, 0.f, 0.f, 0.f);
            if (gr < n) v = *(const float4*)(g_h + (size_t)gr * DH + kc * 32 + c4 * 4);
            float4 sc = *(const float4*)(g_scale + kc * 32 + c4 * 4);
            float4 sh = *(const float4*)(g_shift + kc * 32 + c4 * 4);
            v.x = fmaxf(0.f, fmaf(v.x, sc.x, sh.x));
            v.y = fmaxf(0.f, fmaf(v.y, sc.y, sh.y));
            v.z = fmaxf(0.f, fmaf(v.z, sc.z, sh.z));
            v.w = fmaxf(0.f, fmaf(v.w, sc.w, sh.w));
            *(float4*)&xs[r][c4 * 4] = v;
        }
        __syncthreads();
#pragma unroll
        for (int kk = 0; kk < 32; kk++) {
            float wv = ws[(kc * 32 + kk) * DOUT + tx];
#pragma unroll
            for (int r8 = 0; r8 < 8; r8++)
                acc[r8] = fmaf(xs[ty * 8 + r8][kk], wv, acc[r8]);
        }
        __syncthreads();
    }
#pragma unroll
    for (int r8 = 0; r8 < 8; r8++) {
        int gr = row0 + ty * 8 + r8;
        if (gr < n) g_t[(size_t)gr * DOUT + tx] = acc[r8];
    }
}

// ---------------- fused aggregate + combine + BN stats, F=128. One warp per row. ----------------
__global__ void __launch_bounds__(256) agg_combine128(const float* __restrict__ b, int n) {
    int lane = threadIdx.x & 31;
    int wip  = threadIdx.x >> 5;             // warp in block, 8 warps
    const float4* T = (const float4*)g_t;
    float4 bc = ((const float4*)b)[lane];

    float4 ssum = make_float4(0.f, 0.f, 0.f, 0.f);
    float4 ssq  = make_float4(0.f, 0.f, 0.f, 0.f);

    for (int row = blockIdx.x * 8 + wip; row < n; row += gridDim.x * 8) {
        int start = g_rowstart[row];
        int cnt   = g_deg[row];
        float4 acc = make_float4(0.f, 0.f, 0.f, 0.f);
        for (int j = start; j < start + cnt; j++) {
            int2  pr = g_csr[j];
            float w  = __int_as_float(pr.y);
            float4 v = __ldg(T + (size_t)pr.x * 32 + lane);
            acc.x = fmaf(w, v.x, acc.x);
            acc.y = fmaf(w, v.y, acc.y);
            acc.z = fmaf(w, v.z, acc.z);
            acc.w = fmaf(w, v.w, acc.w);
        }
        float dq = g_disq[row];
        float sn = dq * dq;
        float4 t = __ldg(T + (size_t)row * 32 + lane);
        float4 h;
        h.x = fmaf(sn, t.x, acc.x) + bc.x;
        h.y = fmaf(sn, t.y, acc.y) + bc.y;
        h.z = fmaf(sn, t.z, acc.z) + bc.z;
        h.w = fmaf(sn, t.w, acc.w) + bc.w;
        ((float4*)g_h)[(size_t)row * 32 + lane] = h;
        ssum.x += h.x; ssum.y += h.y; ssum.z += h.z; ssum.w += h.w;
        ssq.x = fmaf(h.x, h.x, ssq.x); ssq.y = fmaf(h.y, h.y, ssq.y);
        ssq.z = fmaf(h.z, h.z, ssq.z); ssq.w = fmaf(h.w, h.w, ssq.w);
    }

    __shared__ float4 sh1[8][32];
    __shared__ float4 sh2[8][32];
    sh1[wip][lane] = ssum;
    sh2[wip][lane] = ssq;
    __syncthreads();
    if (wip == 0) {
        float4 a = sh1[0][lane], q = sh2[0][lane];
#pragma unroll
        for (int w = 1; w < 8; w++) {
            float4 a2 = sh1[w][lane], q2 = sh2[w][lane];
            a.x += a2.x; a.y += a2.y; a.z += a2.z; a.w += a2.w;
            q.x += q2.x; q.y += q2.y; q.z += q2.z; q.w += q2.w;
        }
        red_add_v4(g_stats + lane * 4, a);
        red_add_v4(g_stats + DH + lane * 4, q);
    }
}

// ---------------- BN finalize ----------------
__global__ void bn_finalize(const float* __restrict__ gam, const float* __restrict__ bet, int n) {
    int c = threadIdx.x;
    if (c < DH) {
        float inv_n = 1.0f / (float)n;
        float mu  = g_stats[c] * inv_n;
        float var = g_stats[DH + c] * inv_n - mu * mu;
        float rs  = rsqrtf(var + BN_EPS);
        float sc  = rs * gam[c];
        g_scale[c] = sc;
        g_shift[c] = bet[c] - mu * sc;
    }
}

// ---------------- fused aggregate + combine + log_softmax, F=40. One warp per row. ----------------
__global__ void __launch_bounds__(256) agg40_lsm(const float* __restrict__ b2,
                                                 float* __restrict__ out, int n) {
    int lane = threadIdx.x & 31;
    int wip  = threadIdx.x >> 5;
    const float4* T = (const float4*)g_t;   // n x 10 float4
    bool active = (lane < 10);
    float4 bc = make_float4(0.f, 0.f, 0.f, 0.f);
    if (active) bc = ((const float4*)b2)[lane];

    for (int row = blockIdx.x * 8 + wip; row < n; row += gridDim.x * 8) {
        int start = g_rowstart[row];
        int cnt   = g_deg[row];
        float4 acc = make_float4(0.f, 0.f, 0.f, 0.f);
        for (int j = start; j < start + cnt; j++) {
            int2  pr = g_csr[j];
            float w  = __int_as_float(pr.y);
            if (active) {
                float4 v = __ldg(T + (size_t)pr.x * 10 + lane);
                acc.x = fmaf(w, v.x, acc.x);
                acc.y = fmaf(w, v.y, acc.y);
                acc.z = fmaf(w, v.z, acc.z);
                acc.w = fmaf(w, v.w, acc.w);
            }
        }
        float dq = g_disq[row];
        float sn = dq * dq;
        float4 h = make_float4(-1e30f, -1e30f, -1e30f, -1e30f);
        if (active) {
            float4 t = __ldg(T + (size_t)row * 10 + lane);
            h.x = fmaf(sn, t.x, acc.x) + bc.x;
            h.y = fmaf(sn, t.y, acc.y) + bc.y;
            h.z = fmaf(sn, t.z, acc.z) + bc.z;
            h.w = fmaf(sn, t.w, acc.w) + bc.w;
        }
        // max over 40 values
        float m = fmaxf(fmaxf(h.x, h.y), fmaxf(h.z, h.w));
#pragma unroll
        for (int o = 16; o; o >>= 1) m = fmaxf(m, __shfl_xor_sync(0xFFFFFFFFu, m, o));
        float se = 0.f;
        if (active)
            se = expf(h.x - m) + expf(h.y - m) + expf(h.z - m) + expf(h.w - m);
#pragma unroll
        for (int o = 16; o; o >>= 1) se += __shfl_xor_sync(0xFFFFFFFFu, se, o);
        float lse = m + logf(se);
        if (active) {
            float4 r = make_float4(h.x - lse, h.y - lse, h.z - lse, h.w - lse);
            ((float4*)out)[(size_t)row * 10 + lane] = r;
        }
    }
}

// ---------------- launch ----------------
extern "C" void kernel_launch(void* const* d_in, const int* in_sizes, int n_in,
                              void* d_out, int out_size) {
    const float* x   = (const float*)d_in[0];
    const int*   src = (const int*)d_in[1];
    const int*   dst = (const int*)d_in[2];
    const float* W0  = (const float*)d_in[3];
    const float* b0  = (const float*)d_in[4];
    const float* W1  = (const float*)d_in[5];
    const float* b1  = (const float*)d_in[6];
    const float* W2  = (const float*)d_in[7];
    const float* b2  = (const float*)d_in[8];
    const float* g0  = (const float*)d_in[9];
    const float* be0 = (const float*)d_in[10];
    const float* g1  = (const float*)d_in[11];
    const float* be1 = (const float*)d_in[12];
    float* out = (float*)d_out;

    int n = in_sizes[0] / DH;
    int e = in_sizes[1];
    int nb = (n + SCAN_B - 1) / SCAN_B;

    // ---- CSR build ----
    zero_deg<<<(n + 255) / 256, 256>>>(n);
    count_deg<<<(e + 255) / 256, 256>>>(dst, e);
    calc_disq<<<(n + 255) / 256, 256>>>(n);
    scan1<<<nb, SCAN_B>>>(n);
    scan2<<<1, NB_MAX>>>(nb);
    scan3<<<(n + 255) / 256, 256>>>(n);
    fill_csr<<<(e + 255) / 256, 256>>>(src, dst, e);

    int agg_blocks = 1480;   // 8 warps/block -> ~11840 rows per sweep

    // ---- layer 0 ----
    gemm128<<<(n + 63) / 64, 256>>>(x, W0, n, 0);
    zero_stats<<<1, 256>>>();
    agg_combine128<<<agg_blocks, 256>>>(b0, n);
    bn_finalize<<<1, DH>>>(g0, be0, n);

    // ---- layer 1 ----
    gemm128<<<(n + 63) / 64, 256>>>(nullptr, W1, n, 1);
    zero_stats<<<1, 256>>>();
    agg_combine128<<<agg_blocks, 256>>>(b1, n);
    bn_finalize<<<1, DH>>>(g1, be1, n);

    // ---- layer 2 ----
    gemm40<<<(n + 47) / 48, dim3(DOUT, 6)>>>(W2, n);
    agg40_lsm<<<agg_blocks, 256>>>(b2, out, n);
}